// round 7
// baseline (speedup 1.0000x reference)
#include <cuda_runtime.h>
#include <cuda_bf16.h>
#include <cstdint>

// ---------------------------------------------------------------------------
// out[b,i,j] = sum_d relu(a[b,i,d] + c[b,j,d]) * W2[d] + b2
//   a = emb @ W1[:768] + b1,  c = emb @ W1[768:]
// emb (4,512,768) f32, W1 (1536,256), b1 (256), W2 (256,1), b2 (1)
// out (4,512,512) f32
// ---------------------------------------------------------------------------

#define B_   4
#define N_   512
#define H_   768
#define HID_ 256
#define M_   (B_ * N_)        // 2048

__device__ float g_a[HID_ * M_];                 // d-major: g_a[d*M_+m]
__device__ float g_c[HID_ * M_];
__device__ __nv_bfloat16 g_ehi[M_ * H_];         // emb planes, row-major [m][k]
__device__ __nv_bfloat16 g_elo[M_ * H_];
__device__ __nv_bfloat16 g_bhi[N_ * H_];         // B[n][k], n = half*256 + d
__device__ __nv_bfloat16 g_blo[N_ * H_];

// ---------------- helpers ---------------------------------------------------
__device__ __forceinline__ uint32_t smem_u32(const void* p) {
    uint32_t a;
    asm("{ .reg .u64 t; cvta.to.shared.u64 t, %1; cvt.u32.u64 %0, t; }"
        : "=r"(a) : "l"(p));
    return a;
}
#define SW128(o) ((o) ^ (((o) >> 3) & 0x70))

__device__ __forceinline__ void cp_async16(uint32_t dst, const void* src) {
    asm volatile("cp.async.cg.shared.global [%0], [%1], 16;"
                 :: "r"(dst), "l"(src) : "memory");
}
__device__ __forceinline__ void cp_commit() {
    asm volatile("cp.async.commit_group;" ::: "memory");
}
__device__ __forceinline__ void cp_wait0() {
    asm volatile("cp.async.wait_group 0;" ::: "memory");
}
__device__ __forceinline__ void ldmx4(uint32_t addr, uint32_t* r) {
    asm volatile("ldmatrix.sync.aligned.m8n8.x4.shared.b16 {%0,%1,%2,%3}, [%4];"
                 : "=r"(r[0]), "=r"(r[1]), "=r"(r[2]), "=r"(r[3]) : "r"(addr));
}
__device__ __forceinline__ void mma16816(float* c, const uint32_t* a,
                                         uint32_t b0, uint32_t b1) {
    asm volatile(
        "mma.sync.aligned.m16n8k16.row.col.f32.bf16.bf16.f32 "
        "{%0,%1,%2,%3}, {%4,%5,%6,%7}, {%8,%9}, {%0,%1,%2,%3};"
        : "+f"(c[0]), "+f"(c[1]), "+f"(c[2]), "+f"(c[3])
        : "r"(a[0]), "r"(a[1]), "r"(a[2]), "r"(a[3]), "r"(b0), "r"(b1));
}
// packed fp32x2
__device__ __forceinline__ float2 ffma2(float2 a, float2 b, float2 c) {
    union F2U { float2 f; unsigned long long u; };
    F2U A, Bv, C, D;
    A.f = a; Bv.f = b; C.f = c;
    asm("fma.rn.f32x2 %0, %1, %2, %3;" : "=l"(D.u) : "l"(A.u), "l"(Bv.u), "l"(C.u));
    return D.f;
}
__device__ __forceinline__ float2 fadd2(float2 a, float2 b) {
    union F2U { float2 f; unsigned long long u; };
    F2U A, Bv, D;
    A.f = a; Bv.f = b;
    asm("add.rn.f32x2 %0, %1, %2;" : "=l"(D.u) : "l"(A.u), "l"(Bv.u));
    return D.f;
}

// ---------------------------------------------------------------------------
// Prep 1: split emb (f32) into bf16 hi + lo planes. 4 elems / thread.
// ---------------------------------------------------------------------------
__global__ void __launch_bounds__(256)
emb_split_kernel(const float* __restrict__ emb)
{
    const int idx = (blockIdx.x * 256 + threadIdx.x) * 4;
    float4 v = *(const float4*)&emb[idx];
    __nv_bfloat16 h0 = __float2bfloat16(v.x), h1 = __float2bfloat16(v.y);
    __nv_bfloat16 h2 = __float2bfloat16(v.z), h3 = __float2bfloat16(v.w);
    __nv_bfloat16 l0 = __float2bfloat16(v.x - __bfloat162float(h0));
    __nv_bfloat16 l1 = __float2bfloat16(v.y - __bfloat162float(h1));
    __nv_bfloat16 l2 = __float2bfloat16(v.z - __bfloat162float(h2));
    __nv_bfloat16 l3 = __float2bfloat16(v.w - __bfloat162float(h3));
    *(__nv_bfloat162*)&g_ehi[idx]     = __nv_bfloat162(h0, h1);
    *(__nv_bfloat162*)&g_ehi[idx + 2] = __nv_bfloat162(h2, h3);
    *(__nv_bfloat162*)&g_elo[idx]     = __nv_bfloat162(l0, l1);
    *(__nv_bfloat162*)&g_elo[idx + 2] = __nv_bfloat162(l2, l3);
}

// ---------------------------------------------------------------------------
// Prep 2: W1 (1536 x 256) -> B[n][k] bf16 hi/lo via smem-tiled transpose.
// Tile: 128 k x 32 d per block, both gmem sides coalesced.
// Grid (8 d-tiles, 6 k-tiles, 2 halves) x 256 threads = 96 blocks.
// ---------------------------------------------------------------------------
__global__ void __launch_bounds__(256)
w_split_kernel(const float* __restrict__ W1)
{
    __shared__ float tile[128][33];
    const int d0   = blockIdx.x * 32;
    const int k0   = blockIdx.y * 128;
    const int half = blockIdx.z;
    const int t    = threadIdx.x;

    // load 128 k-rows x 32 d (coalesced: 8 threads x float4 per row)
    {
        const int kk = t >> 3, dd = (t & 7) * 4;
        #pragma unroll
        for (int p = 0; p < 4; p++) {
            float4 v = *(const float4*)&W1[(half * H_ + k0 + kk + p * 32) * HID_ + d0 + dd];
            tile[kk + p * 32][dd]     = v.x;
            tile[kk + p * 32][dd + 1] = v.y;
            tile[kk + p * 32][dd + 2] = v.z;
            tile[kk + p * 32][dd + 3] = v.w;
        }
    }
    __syncthreads();

    // write: 512 chunks of 8 k-values; thread t -> chunks 2t, 2t+1
    #pragma unroll
    for (int e = 0; e < 2; e++) {
        const int cid = t * 2 + e;
        const int nl  = cid >> 4;            // 0..31 (d within tile)
        const int kc  = (cid & 15) * 8;      // k offset within tile
        uint32_t hv[4], lv[4];
        #pragma unroll
        for (int u = 0; u < 4; u++) {
            float x0 = tile[kc + 2*u][nl];
            float x1 = tile[kc + 2*u + 1][nl];
            __nv_bfloat16 h0 = __float2bfloat16(x0);
            __nv_bfloat16 h1 = __float2bfloat16(x1);
            __nv_bfloat16 l0 = __float2bfloat16(x0 - __bfloat162float(h0));
            __nv_bfloat16 l1 = __float2bfloat16(x1 - __bfloat162float(h1));
            __nv_bfloat162 hp(h0, h1), lp(l0, l1);
            hv[u] = *(uint32_t*)&hp;
            lv[u] = *(uint32_t*)&lp;
        }
        const int n = half * HID_ + d0 + nl;
        const int o = n * H_ + k0 + kc;
        *(uint4*)&g_bhi[o] = make_uint4(hv[0], hv[1], hv[2], hv[3]);
        *(uint4*)&g_blo[o] = make_uint4(lv[0], lv[1], lv[2], lv[3]);
    }
}

// ---------------------------------------------------------------------------
// GEMM (unchanged from R6): mma.sync bf16, 3 planes, CTA 128m x 64n, BK=64,
// cp.async double-buffer, SW128 smem. Grid 8 x 16 = 128 CTAs.
// ---------------------------------------------------------------------------
#define GITER 36
#define A_BUF_BYTES (128 * 128)
#define B_BUF_BYTES (64 * 128)

__global__ void __launch_bounds__(256)
gemm_kernel(const float* __restrict__ b1)
{
    __shared__ __align__(1024) unsigned char sraw[2 * A_BUF_BYTES + 2 * B_BUF_BYTES];

    const int t      = threadIdx.x;
    const int lane   = t & 31;
    const int wid    = t >> 5;
    const int warp_m = wid & 3;
    const int warp_n = wid >> 2;
    const int m0     = blockIdx.y * 128;
    const int ng0    = blockIdx.x * 64;
    const int half   = ng0 >> 8;
    const int d0     = ng0 & 255;

    const uint32_t smemA = smem_u32(sraw);
    const uint32_t smemB = smemA + 2 * A_BUF_BYTES;

    auto fill = [&](int buf, int it) {
        const __nv_bfloat16* __restrict__ ea = (it < 24) ? g_ehi : g_elo;
        const __nv_bfloat16* __restrict__ eb =
            (it >= 12 && it < 24) ? g_blo : g_bhi;
        const int k0 = (it % 12) * 64;
        const uint32_t ab = smemA + buf * A_BUF_BYTES;
        const uint32_t bb = smemB + buf * B_BUF_BYTES;
        #pragma unroll
        for (int e = 0; e < 4; e++) {
            const int slot = t + e * 256;
            const int row = slot >> 3, seg = slot & 7;
            const uint32_t off = (uint32_t)(row * 128 + seg * 16);
            cp_async16(ab + SW128(off), &ea[(m0 + row) * H_ + k0 + seg * 8]);
        }
        #pragma unroll
        for (int e = 0; e < 2; e++) {
            const int slot = t + e * 256;
            const int row = slot >> 3, seg = slot & 7;
            const uint32_t off = (uint32_t)(row * 128 + seg * 16);
            cp_async16(bb + SW128(off), &eb[(ng0 + row) * H_ + k0 + seg * 8]);
        }
    };

    const uint32_t csel  = (uint32_t)((lane >> 4) * 16);
    const uint32_t maskx = (uint32_t)((lane & 7) * 16);
    const uint32_t aoff0 = (uint32_t)((warp_m * 32 + (lane & 15)) * 128);
    const uint32_t aoff1 = aoff0 + 16 * 128;
    const uint32_t boff0 = (uint32_t)((warp_n * 32 + (lane & 15)) * 128);
    const uint32_t boff1 = boff0 + 16 * 128;

    float acc[2][4][4];
    #pragma unroll
    for (int mf = 0; mf < 2; mf++)
        #pragma unroll
        for (int nf = 0; nf < 4; nf++)
            #pragma unroll
            for (int e = 0; e < 4; e++) acc[mf][nf][e] = 0.f;

    fill(0, 0);
    cp_commit();
    cp_wait0();
    __syncthreads();

    for (int it = 0; it < GITER; it++) {
        const int cur = it & 1;
        if (it + 1 < GITER) { fill(1 - cur, it + 1); cp_commit(); }

        const uint32_t ab = smemA + cur * A_BUF_BYTES;
        const uint32_t bb = smemB + cur * B_BUF_BYTES;
        #pragma unroll
        for (int kk = 0; kk < 4; kk++) {
            const uint32_t col = ((uint32_t)(kk * 32) + csel) ^ maskx;
            uint32_t a0[4], a1[4], b0[4], b1r[4];
            ldmx4(ab + aoff0 + col, a0);
            ldmx4(ab + aoff1 + col, a1);
            ldmx4(bb + boff0 + col, b0);
            ldmx4(bb + boff1 + col, b1r);
            mma16816(acc[0][0], a0, b0[0],  b0[2]);
            mma16816(acc[0][1], a0, b0[1],  b0[3]);
            mma16816(acc[0][2], a0, b1r[0], b1r[2]);
            mma16816(acc[0][3], a0, b1r[1], b1r[3]);
            mma16816(acc[1][0], a1, b0[0],  b0[2]);
            mma16816(acc[1][1], a1, b0[1],  b0[3]);
            mma16816(acc[1][2], a1, b1r[0], b1r[2]);
            mma16816(acc[1][3], a1, b1r[1], b1r[3]);
        }

        if (it + 1 < GITER) {
            cp_wait0();
            __syncthreads();
        }
    }

    float* __restrict__ gout = half ? g_c : g_a;
    const int mrow = m0 + warp_m * 32 + (lane >> 2);
    #pragma unroll
    for (int mf = 0; mf < 2; mf++) {
        const int m = mrow + mf * 16;
        #pragma unroll
        for (int nf = 0; nf < 4; nf++) {
            const int nl = warp_n * 32 + nf * 8 + (lane & 3) * 2;
            float bias0 = 0.f, bias1 = 0.f;
            if (half == 0) { bias0 = b1[d0 + nl]; bias1 = b1[d0 + nl + 1]; }
            const int d = d0 + nl;
            gout[d       * M_ + m]     = acc[mf][nf][0] + bias0;
            gout[(d + 1) * M_ + m]     = acc[mf][nf][1] + bias1;
            gout[d       * M_ + m + 8] = acc[mf][nf][2] + bias0;
            gout[(d + 1) * M_ + m + 8] = acc[mf][nf][3] + bias1;
        }
    }
}

// ---------------------------------------------------------------------------
// Pair kernel: 32x32 tiles, 64 thr, 4i x 4j/thread, d-major scratch.
// NEW: A tile and W2 stored PRE-DUPLICATED in smem so every packed f32x2
// operand comes out of LDS as an aligned register pair (no MOV repacking).
// ---------------------------------------------------------------------------
#define PDK  32
#define PDIT (HID_ / PDK)   // 8

__global__ void __launch_bounds__(64)
pair_kernel(const float* __restrict__ W2, const float* __restrict__ b2,
            float* __restrict__ out)
{
    const int b  = blockIdx.z;
    const int i0 = blockIdx.y * 32;
    const int j0 = blockIdx.x * 32;
    const int ma = b * N_ + i0;
    const int mc = b * N_ + j0;

    __shared__ float As2[2][PDK][72];   // duplicated: [dk][2m], [dk][2m+1]
    __shared__ float Cs[2][PDK][36];
    __shared__ float Ws2[2 * HID_];     // duplicated: [2d], [2d+1]

    const int t  = threadIdx.x;
    const int tx = t & 7;               // 4 j each
    const int ty = t >> 3;              // 4 i each

    #pragma unroll
    for (int u = 0; u < 4; u++) {
        const float w = W2[t + 64 * u];
        *(float2*)&Ws2[2 * (t + 64 * u)] = make_float2(w, w);
    }

    const int fdk = t >> 1;             // 0..31
    const int fs  = (t & 1) * 16;       // m offset (16 values)

    float4 paf[4], pcf[4];
    auto sts_tile = [&](int nb) {
        #pragma unroll
        for (int e = 0; e < 4; e++) {
            float4 v = paf[e];
            *(float4*)&As2[nb][fdk][2 * (fs + 4 * e)]     =
                make_float4(v.x, v.x, v.y, v.y);
            *(float4*)&As2[nb][fdk][2 * (fs + 4 * e) + 4] =
                make_float4(v.z, v.z, v.w, v.w);
            *(float4*)&Cs[nb][fdk][fs + 4 * e] = pcf[e];
        }
    };

    {
        const float* __restrict__ pa = &g_a[fdk * M_ + ma + fs];
        const float* __restrict__ pc = &g_c[fdk * M_ + mc + fs];
        #pragma unroll
        for (int e = 0; e < 4; e++) { paf[e] = *(const float4*)(pa + 4*e);
                                      pcf[e] = *(const float4*)(pc + 4*e); }
        sts_tile(0);
    }
    __syncthreads();

    float2 acc[4][2];
    #pragma unroll
    for (int mi = 0; mi < 4; mi++) {
        acc[mi][0] = make_float2(0.f, 0.f);
        acc[mi][1] = make_float2(0.f, 0.f);
    }

    for (int it = 0; it < PDIT; it++) {
        const int cur = it & 1;
        if (it + 1 < PDIT) {
            const int dd = (it + 1) * PDK;
            const float* __restrict__ pa = &g_a[(dd + fdk) * M_ + ma + fs];
            const float* __restrict__ pc = &g_c[(dd + fdk) * M_ + mc + fs];
            #pragma unroll
            for (int e = 0; e < 4; e++) { paf[e] = *(const float4*)(pa + 4*e);
                                          pcf[e] = *(const float4*)(pc + 4*e); }
        }

        const int dbase = it * PDK;
        #pragma unroll
        for (int g = 0; g < PDK / 4; g++) {
            const float4 wva = *(const float4*)&Ws2[2 * (dbase + g * 4)];
            const float4 wvb = *(const float4*)&Ws2[2 * (dbase + g * 4) + 4];
            const float2 wp[4] = {
                make_float2(wva.x, wva.y), make_float2(wva.z, wva.w),
                make_float2(wvb.x, wvb.y), make_float2(wvb.z, wvb.w)
            };
            #pragma unroll
            for (int e = 0; e < 4; e++) {
                const int dk = g * 4 + e;
                const float4 a01 = *(const float4*)&As2[cur][dk][ty * 8];
                const float4 a23 = *(const float4*)&As2[cur][dk][ty * 8 + 4];
                const float4 cv  = *(const float4*)&Cs[cur][dk][tx * 4];
                const float2 c01 = make_float2(cv.x, cv.y);
                const float2 c23 = make_float2(cv.z, cv.w);
                const float2 ap[4] = {
                    make_float2(a01.x, a01.y), make_float2(a01.z, a01.w),
                    make_float2(a23.x, a23.y), make_float2(a23.z, a23.w)
                };
                #pragma unroll
                for (int mi = 0; mi < 4; mi++) {
                    float2 s0 = fadd2(ap[mi], c01);
                    float2 s1 = fadd2(ap[mi], c23);
                    s0.x = fmaxf(s0.x, 0.f); s0.y = fmaxf(s0.y, 0.f);
                    s1.x = fmaxf(s1.x, 0.f); s1.y = fmaxf(s1.y, 0.f);
                    acc[mi][0] = ffma2(s0, wp[e], acc[mi][0]);
                    acc[mi][1] = ffma2(s1, wp[e], acc[mi][1]);
                }
            }
        }

        if (it + 1 < PDIT) {
            sts_tile(1 - cur);
            __syncthreads();
        }
    }

    const float bb = b2[0];
    const int j = j0 + tx * 4;
    #pragma unroll
    for (int mi = 0; mi < 4; mi++) {
        const int i = i0 + ty * 4 + mi;
        float4 o;
        o.x = acc[mi][0].x + bb;
        o.y = acc[mi][0].y + bb;
        o.z = acc[mi][1].x + bb;
        o.w = acc[mi][1].y + bb;
        *(float4*)&out[((size_t)b * N_ + i) * N_ + j] = o;
    }
}

// ---------------------------------------------------------------------------
extern "C" void kernel_launch(void* const* d_in, const int* in_sizes, int n_in,
                              void* d_out, int out_size)
{
    const float* emb = (const float*)d_in[0];
    const float* W1  = (const float*)d_in[1];
    const float* b1  = (const float*)d_in[2];
    const float* W2  = (const float*)d_in[3];
    const float* b2  = (const float*)d_in[4];
    float* out = (float*)d_out;

    emb_split_kernel<<<(M_ * H_) / (256 * 4), 256>>>(emb);   // 1536 blocks
    {
        dim3 wgrid(HID_ / 32, H_ / 128, 2);                  // 8 x 6 x 2 = 96
        w_split_kernel<<<wgrid, 256>>>(W1);
    }

    dim3 ggrid(N_ / 64, M_ / 128);                           // 8 x 16 = 128
    gemm_kernel<<<ggrid, 256>>>(b1);

    dim3 pgrid(N_ / 32, N_ / 32, B_);                        // 16 x 16 x 4
    pair_kernel<<<pgrid, 64>>>(W2, b2, out);
}

// round 8
// speedup vs baseline: 1.1820x; 1.1820x over previous
#include <cuda_runtime.h>
#include <cuda_bf16.h>
#include <cstdint>

// ---------------------------------------------------------------------------
// out[b,i,j] = sum_d relu(a[b,i,d] + c[b,j,d]) * W2[d] + b2
//   a = emb @ W1[:768] + b1,  c = emb @ W1[768:]
// emb (4,512,768) f32, W1 (1536,256), b1 (256), W2 (256,1), b2 (1)
// out (4,512,512) f32
// ---------------------------------------------------------------------------

#define B_   4
#define N_   512
#define H_   768
#define HID_ 256
#define M_   (B_ * N_)        // 2048

__device__ float g_a[HID_ * M_];                 // d-major: g_a[d*M_+m]
__device__ float g_c[HID_ * M_];
__device__ __nv_bfloat16 g_ehi[M_ * H_];         // emb planes, row-major [m][k]
__device__ __nv_bfloat16 g_elo[M_ * H_];
__device__ __nv_bfloat16 g_bhi[N_ * H_];         // B[n][k], n = half*256 + d
__device__ __nv_bfloat16 g_blo[N_ * H_];

// ---------------- helpers ---------------------------------------------------
__device__ __forceinline__ uint32_t smem_u32(const void* p) {
    uint32_t a;
    asm("{ .reg .u64 t; cvta.to.shared.u64 t, %1; cvt.u32.u64 %0, t; }"
        : "=r"(a) : "l"(p));
    return a;
}
#define SW128(o) ((o) ^ (((o) >> 3) & 0x70))

__device__ __forceinline__ void cp_async16(uint32_t dst, const void* src) {
    asm volatile("cp.async.cg.shared.global [%0], [%1], 16;"
                 :: "r"(dst), "l"(src) : "memory");
}
__device__ __forceinline__ void cp_commit() {
    asm volatile("cp.async.commit_group;" ::: "memory");
}
__device__ __forceinline__ void cp_wait0() {
    asm volatile("cp.async.wait_group 0;" ::: "memory");
}
__device__ __forceinline__ void ldmx4(uint32_t addr, uint32_t* r) {
    asm volatile("ldmatrix.sync.aligned.m8n8.x4.shared.b16 {%0,%1,%2,%3}, [%4];"
                 : "=r"(r[0]), "=r"(r[1]), "=r"(r[2]), "=r"(r[3]) : "r"(addr));
}
__device__ __forceinline__ void mma16816(float* c, const uint32_t* a,
                                         uint32_t b0, uint32_t b1) {
    asm volatile(
        "mma.sync.aligned.m16n8k16.row.col.f32.bf16.bf16.f32 "
        "{%0,%1,%2,%3}, {%4,%5,%6,%7}, {%8,%9}, {%0,%1,%2,%3};"
        : "+f"(c[0]), "+f"(c[1]), "+f"(c[2]), "+f"(c[3])
        : "r"(a[0]), "r"(a[1]), "r"(a[2]), "r"(a[3]), "r"(b0), "r"(b1));
}
// packed fp32x2
__device__ __forceinline__ float2 ffma2(float2 a, float2 b, float2 c) {
    union F2U { float2 f; unsigned long long u; };
    F2U A, Bv, C, D;
    A.f = a; Bv.f = b; C.f = c;
    asm("fma.rn.f32x2 %0, %1, %2, %3;" : "=l"(D.u) : "l"(A.u), "l"(Bv.u), "l"(C.u));
    return D.f;
}
__device__ __forceinline__ float2 fadd2(float2 a, float2 b) {
    union F2U { float2 f; unsigned long long u; };
    F2U A, Bv, D;
    A.f = a; Bv.f = b;
    asm("add.rn.f32x2 %0, %1, %2;" : "=l"(D.u) : "l"(A.u), "l"(Bv.u));
    return D.f;
}

// ---------------------------------------------------------------------------
// Prep 1: split emb (f32) into bf16 hi + lo planes. 4 elems / thread.
// ---------------------------------------------------------------------------
__global__ void __launch_bounds__(256)
emb_split_kernel(const float* __restrict__ emb)
{
    const int idx = (blockIdx.x * 256 + threadIdx.x) * 4;
    float4 v = *(const float4*)&emb[idx];
    __nv_bfloat16 h0 = __float2bfloat16(v.x), h1 = __float2bfloat16(v.y);
    __nv_bfloat16 h2 = __float2bfloat16(v.z), h3 = __float2bfloat16(v.w);
    __nv_bfloat16 l0 = __float2bfloat16(v.x - __bfloat162float(h0));
    __nv_bfloat16 l1 = __float2bfloat16(v.y - __bfloat162float(h1));
    __nv_bfloat16 l2 = __float2bfloat16(v.z - __bfloat162float(h2));
    __nv_bfloat16 l3 = __float2bfloat16(v.w - __bfloat162float(h3));
    *(__nv_bfloat162*)&g_ehi[idx]     = __nv_bfloat162(h0, h1);
    *(__nv_bfloat162*)&g_ehi[idx + 2] = __nv_bfloat162(h2, h3);
    *(__nv_bfloat162*)&g_elo[idx]     = __nv_bfloat162(l0, l1);
    *(__nv_bfloat162*)&g_elo[idx + 2] = __nv_bfloat162(l2, l3);
}

// ---------------------------------------------------------------------------
// Prep 2: W1 (1536 x 256) -> B[n][k] bf16 hi/lo via smem-tiled transpose.
// ---------------------------------------------------------------------------
__global__ void __launch_bounds__(256)
w_split_kernel(const float* __restrict__ W1)
{
    __shared__ float tile[128][33];
    const int d0   = blockIdx.x * 32;
    const int k0   = blockIdx.y * 128;
    const int half = blockIdx.z;
    const int t    = threadIdx.x;

    {
        const int kk = t >> 3, dd = (t & 7) * 4;
        #pragma unroll
        for (int p = 0; p < 4; p++) {
            float4 v = *(const float4*)&W1[(half * H_ + k0 + kk + p * 32) * HID_ + d0 + dd];
            tile[kk + p * 32][dd]     = v.x;
            tile[kk + p * 32][dd + 1] = v.y;
            tile[kk + p * 32][dd + 2] = v.z;
            tile[kk + p * 32][dd + 3] = v.w;
        }
    }
    __syncthreads();

    #pragma unroll
    for (int e = 0; e < 2; e++) {
        const int cid = t * 2 + e;
        const int nl  = cid >> 4;
        const int kc  = (cid & 15) * 8;
        uint32_t hv[4], lv[4];
        #pragma unroll
        for (int u = 0; u < 4; u++) {
            float x0 = tile[kc + 2*u][nl];
            float x1 = tile[kc + 2*u + 1][nl];
            __nv_bfloat16 h0 = __float2bfloat16(x0);
            __nv_bfloat16 h1 = __float2bfloat16(x1);
            __nv_bfloat16 l0 = __float2bfloat16(x0 - __bfloat162float(h0));
            __nv_bfloat16 l1 = __float2bfloat16(x1 - __bfloat162float(h1));
            __nv_bfloat162 hp(h0, h1), lp(l0, l1);
            hv[u] = *(uint32_t*)&hp;
            lv[u] = *(uint32_t*)&lp;
        }
        const int n = half * HID_ + d0 + nl;
        const int o = n * H_ + k0 + kc;
        *(uint4*)&g_bhi[o] = make_uint4(hv[0], hv[1], hv[2], hv[3]);
        *(uint4*)&g_blo[o] = make_uint4(lv[0], lv[1], lv[2], lv[3]);
    }
}

// ---------------------------------------------------------------------------
// GEMM (unchanged): mma.sync bf16, 3 planes, CTA 128m x 64n, BK=64,
// cp.async double-buffer, SW128 smem. Grid 8 x 16 = 128 CTAs.
// ---------------------------------------------------------------------------
#define GITER 36
#define A_BUF_BYTES (128 * 128)
#define B_BUF_BYTES (64 * 128)

__global__ void __launch_bounds__(256)
gemm_kernel(const float* __restrict__ b1)
{
    __shared__ __align__(1024) unsigned char sraw[2 * A_BUF_BYTES + 2 * B_BUF_BYTES];

    const int t      = threadIdx.x;
    const int lane   = t & 31;
    const int wid    = t >> 5;
    const int warp_m = wid & 3;
    const int warp_n = wid >> 2;
    const int m0     = blockIdx.y * 128;
    const int ng0    = blockIdx.x * 64;
    const int half   = ng0 >> 8;
    const int d0     = ng0 & 255;

    const uint32_t smemA = smem_u32(sraw);
    const uint32_t smemB = smemA + 2 * A_BUF_BYTES;

    auto fill = [&](int buf, int it) {
        const __nv_bfloat16* __restrict__ ea = (it < 24) ? g_ehi : g_elo;
        const __nv_bfloat16* __restrict__ eb =
            (it >= 12 && it < 24) ? g_blo : g_bhi;
        const int k0 = (it % 12) * 64;
        const uint32_t ab = smemA + buf * A_BUF_BYTES;
        const uint32_t bb = smemB + buf * B_BUF_BYTES;
        #pragma unroll
        for (int e = 0; e < 4; e++) {
            const int slot = t + e * 256;
            const int row = slot >> 3, seg = slot & 7;
            const uint32_t off = (uint32_t)(row * 128 + seg * 16);
            cp_async16(ab + SW128(off), &ea[(m0 + row) * H_ + k0 + seg * 8]);
        }
        #pragma unroll
        for (int e = 0; e < 2; e++) {
            const int slot = t + e * 256;
            const int row = slot >> 3, seg = slot & 7;
            const uint32_t off = (uint32_t)(row * 128 + seg * 16);
            cp_async16(bb + SW128(off), &eb[(ng0 + row) * H_ + k0 + seg * 8]);
        }
    };

    const uint32_t csel  = (uint32_t)((lane >> 4) * 16);
    const uint32_t maskx = (uint32_t)((lane & 7) * 16);
    const uint32_t aoff0 = (uint32_t)((warp_m * 32 + (lane & 15)) * 128);
    const uint32_t aoff1 = aoff0 + 16 * 128;
    const uint32_t boff0 = (uint32_t)((warp_n * 32 + (lane & 15)) * 128);
    const uint32_t boff1 = boff0 + 16 * 128;

    float acc[2][4][4];
    #pragma unroll
    for (int mf = 0; mf < 2; mf++)
        #pragma unroll
        for (int nf = 0; nf < 4; nf++)
            #pragma unroll
            for (int e = 0; e < 4; e++) acc[mf][nf][e] = 0.f;

    fill(0, 0);
    cp_commit();
    cp_wait0();
    __syncthreads();

    for (int it = 0; it < GITER; it++) {
        const int cur = it & 1;
        if (it + 1 < GITER) { fill(1 - cur, it + 1); cp_commit(); }

        const uint32_t ab = smemA + cur * A_BUF_BYTES;
        const uint32_t bb = smemB + cur * B_BUF_BYTES;
        #pragma unroll
        for (int kk = 0; kk < 4; kk++) {
            const uint32_t col = ((uint32_t)(kk * 32) + csel) ^ maskx;
            uint32_t a0[4], a1[4], b0[4], b1r[4];
            ldmx4(ab + aoff0 + col, a0);
            ldmx4(ab + aoff1 + col, a1);
            ldmx4(bb + boff0 + col, b0);
            ldmx4(bb + boff1 + col, b1r);
            mma16816(acc[0][0], a0, b0[0],  b0[2]);
            mma16816(acc[0][1], a0, b0[1],  b0[3]);
            mma16816(acc[0][2], a0, b1r[0], b1r[2]);
            mma16816(acc[0][3], a0, b1r[1], b1r[3]);
            mma16816(acc[1][0], a1, b0[0],  b0[2]);
            mma16816(acc[1][1], a1, b0[1],  b0[3]);
            mma16816(acc[1][2], a1, b1r[0], b1r[2]);
            mma16816(acc[1][3], a1, b1r[1], b1r[3]);
        }

        if (it + 1 < GITER) {
            cp_wait0();
            __syncthreads();
        }
    }

    float* __restrict__ gout = half ? g_c : g_a;
    const int mrow = m0 + warp_m * 32 + (lane >> 2);
    #pragma unroll
    for (int mf = 0; mf < 2; mf++) {
        const int m = mrow + mf * 16;
        #pragma unroll
        for (int nf = 0; nf < 4; nf++) {
            const int nl = warp_n * 32 + nf * 8 + (lane & 3) * 2;
            float bias0 = 0.f, bias1 = 0.f;
            if (half == 0) { bias0 = b1[d0 + nl]; bias1 = b1[d0 + nl + 1]; }
            const int d = d0 + nl;
            gout[d       * M_ + m]     = acc[mf][nf][0] + bias0;
            gout[(d + 1) * M_ + m]     = acc[mf][nf][1] + bias1;
            gout[d       * M_ + m + 8] = acc[mf][nf][2] + bias0;
            gout[(d + 1) * M_ + m + 8] = acc[mf][nf][3] + bias1;
        }
    }
}

// ---------------------------------------------------------------------------
// Pair kernel, SPLIT-D: 32x32 output tile, 128 threads (4 warps).
// Warps 0-1 accumulate d in [0,128), warps 2-3 d in [128,256); smem reduction
// combines. cp.async double-buffered tile fills (no prefetch registers).
// PDK=16 per step, 8 steps per half. Grid 16x16x4 = 1024 blocks, 1 wave.
// ---------------------------------------------------------------------------
#define PDK    16
#define PITERS 8          // 128 / PDK per half
#define PA_HB  (PDK * 32 * 4)            // bytes per (buf,half) tile: 2KB
#define PA_BUF (2 * PA_HB)               // per buf (2 halves): 4KB

__global__ void __launch_bounds__(128, 7)
pair_kernel(const float* __restrict__ W2, const float* __restrict__ b2,
            float* __restrict__ out)
{
    __shared__ __align__(16) float As[2][2][PDK][32];   // [buf][half][dk][m] 8KB
    __shared__ __align__(16) float Cs[2][2][PDK][32];   // 8KB
    __shared__ float Ws2[2 * HID_];                     // duplicated pairs, 2KB
    __shared__ float red[64][20];                       // reduction scratch 5KB

    const int b  = blockIdx.z;
    const int i0 = blockIdx.y * 32;
    const int j0 = blockIdx.x * 32;
    const int ma = b * N_ + i0;
    const int mc = b * N_ + j0;

    const int t  = threadIdx.x;        // 128
    const int hd = t >> 6;             // d-half: 0 or 1
    const int tx = t & 7;              // 4 j each
    const int ty = (t >> 3) & 7;       // 4 i each

    // W2 duplicated pairs
    #pragma unroll
    for (int u = 0; u < 2; u++) {
        const float w = W2[t + 128 * u];
        *(float2*)&Ws2[2 * (t + 128 * u)] = make_float2(w, w);
    }

    const uint32_t sA = smem_u32(As);
    const uint32_t sC = smem_u32(Cs);

    // cp.async fill: per buffer, A needs 256 x 16B chunks (2 halves x 16dk x 8seg)
    auto fill = [&](int buf, int it) {
        #pragma unroll
        for (int e = 0; e < 2; e++) {
            const int c  = t + e * 128;           // 0..255
            const int h  = c >> 7;
            const int dk = (c >> 3) & 15;
            const int sg = c & 7;
            const int d  = h * 128 + it * PDK + dk;
            const uint32_t dst = (uint32_t)(buf * PA_BUF + c * 16);
            cp_async16(sA + dst, &g_a[d * M_ + ma + sg * 4]);
            cp_async16(sC + dst, &g_c[d * M_ + mc + sg * 4]);
        }
    };

    fill(0, 0);
    cp_commit();
    cp_wait0();
    __syncthreads();

    float2 acc[4][2];
    #pragma unroll
    for (int mi = 0; mi < 4; mi++) {
        acc[mi][0] = make_float2(0.f, 0.f);
        acc[mi][1] = make_float2(0.f, 0.f);
    }

    for (int it = 0; it < PITERS; it++) {
        const int cur = it & 1;
        if (it + 1 < PITERS) { fill(1 - cur, it + 1); cp_commit(); }

        const int dbase = hd * 128 + it * PDK;
        #pragma unroll
        for (int g = 0; g < PDK / 4; g++) {
            const float4 wva = *(const float4*)&Ws2[2 * (dbase + g * 4)];
            const float4 wvb = *(const float4*)&Ws2[2 * (dbase + g * 4) + 4];
            const float2 wp[4] = {
                make_float2(wva.x, wva.y), make_float2(wva.z, wva.w),
                make_float2(wvb.x, wvb.y), make_float2(wvb.z, wvb.w)
            };
            #pragma unroll
            for (int e = 0; e < 4; e++) {
                const int dk = g * 4 + e;
                const float4 av = *(const float4*)&As[cur][hd][dk][ty * 4];
                const float4 cv = *(const float4*)&Cs[cur][hd][dk][tx * 4];
                const float2 c01 = make_float2(cv.x, cv.y);
                const float2 c23 = make_float2(cv.z, cv.w);
                const float am[4] = {av.x, av.y, av.z, av.w};
                #pragma unroll
                for (int mi = 0; mi < 4; mi++) {
                    const float2 ap = make_float2(am[mi], am[mi]);
                    float2 s0 = fadd2(ap, c01);
                    float2 s1 = fadd2(ap, c23);
                    s0.x = fmaxf(s0.x, 0.f); s0.y = fmaxf(s0.y, 0.f);
                    s1.x = fmaxf(s1.x, 0.f); s1.y = fmaxf(s1.y, 0.f);
                    acc[mi][0] = ffma2(s0, wp[e], acc[mi][0]);
                    acc[mi][1] = ffma2(s1, wp[e], acc[mi][1]);
                }
            }
        }

        if (it + 1 < PITERS) {
            cp_wait0();
            __syncthreads();
        }
    }

    // cross-half reduction: upper half stores, lower half combines + writes
    if (t >= 64) {
        const int u = t - 64;
        #pragma unroll
        for (int mi = 0; mi < 4; mi++)
            *(float4*)&red[u][mi * 4] =
                make_float4(acc[mi][0].x, acc[mi][0].y,
                            acc[mi][1].x, acc[mi][1].y);
    }
    __syncthreads();
    if (t < 64) {
        const float bb = b2[0];
        const int j = j0 + tx * 4;
        #pragma unroll
        for (int mi = 0; mi < 4; mi++) {
            const float4 r = *(const float4*)&red[t][mi * 4];
            const int i = i0 + ty * 4 + mi;
            float4 o;
            o.x = acc[mi][0].x + r.x + bb;
            o.y = acc[mi][0].y + r.y + bb;
            o.z = acc[mi][1].x + r.z + bb;
            o.w = acc[mi][1].y + r.w + bb;
            *(float4*)&out[((size_t)b * N_ + i) * N_ + j] = o;
        }
    }
}

// ---------------------------------------------------------------------------
extern "C" void kernel_launch(void* const* d_in, const int* in_sizes, int n_in,
                              void* d_out, int out_size)
{
    const float* emb = (const float*)d_in[0];
    const float* W1  = (const float*)d_in[1];
    const float* b1  = (const float*)d_in[2];
    const float* W2  = (const float*)d_in[3];
    const float* b2  = (const float*)d_in[4];
    float* out = (float*)d_out;

    emb_split_kernel<<<(M_ * H_) / (256 * 4), 256>>>(emb);   // 1536 blocks
    {
        dim3 wgrid(HID_ / 32, H_ / 128, 2);                  // 8 x 6 x 2 = 96
        w_split_kernel<<<wgrid, 256>>>(W1);
    }

    dim3 ggrid(N_ / 64, M_ / 128);                           // 8 x 16 = 128
    gemm_kernel<<<ggrid, 256>>>(b1);

    dim3 pgrid(N_ / 32, N_ / 32, B_);                        // 16 x 16 x 4
    pair_kernel<<<pgrid, 128>>>(W2, b2, out);
}